// round 5
// baseline (speedup 1.0000x reference)
#include <cuda_runtime.h>

#define NUM_CAT   16
#define NUM_ATTR  144
#define NUM_NUM   128
#define N_ARY     32
#define NUM_SEG   100000
#define N_ROWS    1000000

// Scratch (device globals — no allocation allowed in kernel_launch)
__device__ __align__(16) float g_agg[NUM_SEG * N_ARY];   // 12.8 MB, L2-resident
__device__ int   g_catidx[N_ROWS];                        // compact per-row segment id
__device__ float g_conf[N_ARY];                           // conf by OUTPUT rank
__device__ int   g_cols_sorted[N_ARY];                    // selected input columns, ascending
__device__ int   g_slot_of_rank[N_ARY];                   // rank k -> slot in sorted order
__device__ int   g_catcol;

// ---------------------------------------------------------------------------
// Kernel 0: softmaxes + top-k selection (tiny; single thread, ~4K flops)
// ---------------------------------------------------------------------------
__global__ void k_setup(const float* __restrict__ cat_mask,
                        const float* __restrict__ num_mask) {
    if (blockIdx.x != 0 || threadIdx.x != 0) return;

    // --- categorical softmax, top-1 ---
    float c[NUM_CAT];
    float m = -1e30f;
    for (int i = 0; i < NUM_CAT; i++) { c[i] = cat_mask[i]; m = fmaxf(m, c[i]); }
    float s = 0.f;
    for (int i = 0; i < NUM_CAT; i++) { c[i] = expf(c[i] - m); s += c[i]; }
    float inv_s = 1.0f / s;
    float top_cat_val = -1.f; int top_cat_idx = 0;
    for (int i = 0; i < NUM_CAT; i++) {
        float p = c[i] * inv_s;
        if (p > top_cat_val) { top_cat_val = p; top_cat_idx = i; }  // first-index tie-break (matches top_k)
    }
    g_catcol = top_cat_idx;

    // --- numeric softmax, top-32 (descending, first-index tie-break) ---
    float n[NUM_NUM];
    float m2 = -1e30f;
    for (int j = 0; j < NUM_NUM; j++) { n[j] = num_mask[j]; m2 = fmaxf(m2, n[j]); }
    float s2 = 0.f;
    for (int j = 0; j < NUM_NUM; j++) { n[j] = expf(n[j] - m2); s2 += n[j]; }
    float inv_s2 = 1.0f / s2;
    for (int j = 0; j < NUM_NUM; j++) n[j] *= inv_s2;

    int sel_col[N_ARY];     // numeric column index by rank
    bool used[NUM_NUM];
    for (int j = 0; j < NUM_NUM; j++) used[j] = false;
    for (int k = 0; k < N_ARY; k++) {
        float best = -1.f; int bj = 0;
        for (int j = 0; j < NUM_NUM; j++) {
            if (!used[j] && n[j] > best) { best = n[j]; bj = j; }
        }
        used[bj] = true;
        sel_col[k] = bj;
        g_conf[k]  = 0.5f * (best + top_cat_val);
    }

    // Sort selected columns ascending (for scatter load locality), keep
    // rank -> slot mapping for the gather.
    int order[N_ARY];                      // slot s holds rank order[s]
    for (int s = 0; s < N_ARY; s++) order[s] = s;
    for (int a = 0; a < N_ARY - 1; a++) {           // selection sort (32 elems)
        int mn = a;
        for (int b = a + 1; b < N_ARY; b++)
            if (sel_col[order[b]] < sel_col[order[mn]]) mn = b;
        int t = order[a]; order[a] = order[mn]; order[mn] = t;
    }
    for (int s = 0; s < N_ARY; s++) {
        int rank = order[s];
        g_cols_sorted[s]     = NUM_CAT + sel_col[rank];  // absolute input column
        g_slot_of_rank[rank] = s;
    }
}

// ---------------------------------------------------------------------------
// Kernel 1: zero the aggregation table (runs every graph replay)
// ---------------------------------------------------------------------------
__global__ void k_zero() {
    int i = blockIdx.x * blockDim.x + threadIdx.x;   // grid sized exactly
    reinterpret_cast<float4*>(g_agg)[i] = make_float4(0.f, 0.f, 0.f, 0.f);
}

// ---------------------------------------------------------------------------
// Kernel 2: scatter-add. 8 threads per row; each thread owns 4 consecutive
// slots of the 32 sorted columns and issues ONE red.global.add.v4.f32 into
// the compact agg table -> 8M vector reductions instead of 32M scalar ones.
// Every thread loads its own seg (lanes of a group share the address -> L1
// broadcast; same sector traffic as a shfl-broadcast, but no warp-collective).
// idx_inputs is INT32 on device (JAX x64 off); seg clamped so a dtype
// surprise yields rel_err, not a crash.
// ---------------------------------------------------------------------------
__global__ void k_scatter(const float* __restrict__ inputs,
                          const int* __restrict__ idx_inputs) {
    __shared__ int s_cols[N_ARY];
    __shared__ int s_catcol;
    if (threadIdx.x < N_ARY) s_cols[threadIdx.x] = g_cols_sorted[threadIdx.x];
    if (threadIdx.x == 0)    s_catcol = g_catcol;
    __syncthreads();

    unsigned gid = blockIdx.x * blockDim.x + threadIdx.x;  // exact grid: N_ROWS*8
    int r = (int)(gid >> 3);
    int g = (int)(gid & 7u);

    int seg = idx_inputs[(size_t)r * NUM_CAT + s_catcol];  // broadcast within 8-lane group
    seg = min(max(seg, 0), NUM_SEG - 1);                   // defensive: never OOB
    if (g == 0) g_catidx[r] = seg;                         // compact copy for gather pass

    const float* row = inputs + (size_t)r * NUM_ATTR;
    int c0 = s_cols[4 * g + 0];
    int c1 = s_cols[4 * g + 1];
    int c2 = s_cols[4 * g + 2];
    int c3 = s_cols[4 * g + 3];
    float v0 = row[c0];
    float v1 = row[c1];
    float v2 = row[c2];
    float v3 = row[c3];

    float* dst = &g_agg[(size_t)seg * N_ARY + 4 * g];    // 16B-aligned
    asm volatile("red.global.add.v4.f32 [%0], {%1,%2,%3,%4};"
                 :: "l"(dst), "f"(v0), "f"(v1), "f"(v2), "f"(v3)
                 : "memory");
}

// ---------------------------------------------------------------------------
// Kernel 3: gather + scale. Lane j (== output rank j) reads the slot where
// rank j's column was aggregated, scales by conf[j], writes coalesced 128B
// per row. 8 rows per warp for index-load batching (MLP).
// ---------------------------------------------------------------------------
__global__ void k_gather(float* __restrict__ out) {
    __shared__ int   s_slot[N_ARY];
    __shared__ float s_conf[N_ARY];
    if (threadIdx.x < N_ARY) {
        s_slot[threadIdx.x] = g_slot_of_rank[threadIdx.x];
        s_conf[threadIdx.x] = g_conf[threadIdx.x];
    }
    __syncthreads();

    int warpId = threadIdx.x >> 5;
    int lane   = threadIdx.x & 31;
    int  slot  = s_slot[lane];
    float conf = s_conf[lane];

    int base_row = (blockIdx.x * 8 + warpId) * 8;   // 8 warps/block, 8 rows/warp

    int segs[8];
#pragma unroll
    for (int k = 0; k < 8; k++) segs[k] = g_catidx[base_row + k];   // batched for MLP

#pragma unroll
    for (int k = 0; k < 8; k++) {
        int r = base_row + k;
        out[(size_t)r * N_ARY + lane] =
            g_agg[(size_t)segs[k] * N_ARY + slot] * conf;
    }
}

// ---------------------------------------------------------------------------
extern "C" void kernel_launch(void* const* d_in, const int* in_sizes, int n_in,
                              void* d_out, int out_size) {
    const float* inputs     = (const float*)d_in[0];
    const int*   idx_inputs = (const int*)d_in[1];     // int32 (JAX x64 off)
    const float* cat_mask   = (const float*)d_in[2];
    const float* num_mask   = (const float*)d_in[3];
    float*       out        = (float*)d_out;

    k_setup<<<1, 32>>>(cat_mask, num_mask);
    k_zero<<<(NUM_SEG * N_ARY / 4) / 256, 256>>>();                 // 3125 blocks
    k_scatter<<<(N_ROWS * 8) / 256, 256>>>(inputs, idx_inputs);     // 31250 blocks
    k_gather<<<N_ROWS / 64, 256>>>(out);                            // 15625 blocks
}

// round 6
// speedup vs baseline: 1.3567x; 1.3567x over previous
#include <cuda_runtime.h>

#define NUM_CAT   16
#define NUM_ATTR  144
#define NUM_NUM   128
#define N_ARY     32
#define NUM_SEG   100000
#define N_ROWS    1000000

// Scratch (device globals — no allocation allowed in kernel_launch)
__device__ __align__(16) float g_agg[NUM_SEG * N_ARY];   // 12.8 MB, L2-resident
__device__ int   g_catidx[N_ROWS];                        // compact per-row segment id
__device__ float g_conf[N_ARY];                           // conf by OUTPUT rank
__device__ int   g_cols_sorted[N_ARY];                    // selected NUMERIC col (0..127), ascending
__device__ int   g_slot_of_rank[N_ARY];                   // rank k -> slot in sorted order
__device__ int   g_catcol;

// ---------------------------------------------------------------------------
// Kernel 0: fused init. Block 0 / warp 0: warp-parallel softmax + top-k
// (shfl reductions, ~2k cycles instead of ~150k single-threaded).
// Blocks 1..3125: zero the agg table (runs every graph replay).
// ---------------------------------------------------------------------------
__global__ void k_init(const float* __restrict__ cat_mask,
                       const float* __restrict__ num_mask) {
    const unsigned FULL = 0xffffffffu;

    if (blockIdx.x > 0) {
        int i = (blockIdx.x - 1) * blockDim.x + threadIdx.x;   // 3125*256 = 800k float4
        reinterpret_cast<float4*>(g_agg)[i] = make_float4(0.f, 0.f, 0.f, 0.f);
        return;
    }
    if (threadIdx.x >= 32) return;
    int lane = threadIdx.x;

    // --- categorical softmax + top-1 (16 values across lanes 0..15) ---
    float cv = (lane < NUM_CAT) ? cat_mask[lane] : -1e30f;
    float cm = cv;
    for (int o = 16; o; o >>= 1) cm = fmaxf(cm, __shfl_xor_sync(FULL, cm, o));
    float ce = (lane < NUM_CAT) ? expf(cv - cm) : 0.f;
    float cs = ce;
    for (int o = 16; o; o >>= 1) cs += __shfl_xor_sync(FULL, cs, o);
    float cp = ce / cs;
    float bv = cp; int bi = lane;
    for (int o = 16; o; o >>= 1) {               // argmax, first-index tie-break
        float ov = __shfl_xor_sync(FULL, bv, o);
        int   oi = __shfl_xor_sync(FULL, bi, o);
        if (ov > bv || (ov == bv && oi < bi)) { bv = ov; bi = oi; }
    }
    float top_cat_val = bv;                      // all lanes hold it
    if (lane == 0) g_catcol = bi;

    // --- numeric softmax (128 values: lane holds cols lane+32j) ---
    float nv[4];
#pragma unroll
    for (int j = 0; j < 4; j++) nv[j] = num_mask[lane + 32 * j];
    float nm = fmaxf(fmaxf(nv[0], nv[1]), fmaxf(nv[2], nv[3]));
    for (int o = 16; o; o >>= 1) nm = fmaxf(nm, __shfl_xor_sync(FULL, nm, o));
    float ns = 0.f;
#pragma unroll
    for (int j = 0; j < 4; j++) { nv[j] = expf(nv[j] - nm); ns += nv[j]; }
    for (int o = 16; o; o >>= 1) ns += __shfl_xor_sync(FULL, ns, o);
    float inv = 1.f / ns;
#pragma unroll
    for (int j = 0; j < 4; j++) nv[j] *= inv;    // probs > 0, so -1 marks "used"

    // --- top-32: 32 warp-argmax rounds; lane k keeps rank-k (col,val) ---
    int my_col = 0; float my_val = 0.f;
    for (int k = 0; k < N_ARY; k++) {
        float lb = nv[0]; int lj = 0;            // local best, smallest col on tie
#pragma unroll
        for (int j = 1; j < 4; j++) if (nv[j] > lb) { lb = nv[j]; lj = j; }
        float gv = lb; int gc = lane + 32 * lj;
        for (int o = 16; o; o >>= 1) {           // global: max val, smallest col on tie
            float ov = __shfl_xor_sync(FULL, gv, o);
            int   oc = __shfl_xor_sync(FULL, gc, o);
            if (ov > gv || (ov == gv && oc < gc)) { gv = ov; gc = oc; }
        }
        if (lane == k) { my_col = gc; my_val = gv; }
        if ((gc & 31) == lane) nv[gc >> 5] = -1.f;   // mark used at owner lane
    }

    g_conf[lane] = 0.5f * (my_val + top_cat_val);

    // rank of my_col among the 32 selected (ascending; cols are distinct)
    int rank = 0;
    for (int j = 0; j < N_ARY; j++) {
        int oc = __shfl_sync(FULL, my_col, j);
        rank += (oc < my_col);
    }
    g_cols_sorted[rank]  = my_col;               // numeric-relative (0..127)
    g_slot_of_rank[lane] = rank;
}

// ---------------------------------------------------------------------------
// Kernel 1: scatter-add. Warp handles 4 rows:
//   phase 1: coalesced float4 load of each row's 128-float numeric segment
//            (4 wavefronts/LDG vs ~16 for the scattered-scalar version)
//   phase 2: park rows in padded shared (132-float stride breaks the 512B
//            bank aliasing between the 4 row groups)
//   phase 3: 8 lanes per row each pick 4 sorted columns from LDS and issue
//            ONE red.global.add.v4.f32 into the L2-resident agg table.
// ---------------------------------------------------------------------------
__global__ void k_scatter(const float* __restrict__ inputs,
                          const int* __restrict__ idx_inputs) {
    __shared__ __align__(16) float s_row[8][4][132];   // 8 warps x 4 rows, +4 pad
    __shared__ int s_cols[N_ARY];
    __shared__ int s_catcol;
    if (threadIdx.x < N_ARY)  s_cols[threadIdx.x] = g_cols_sorted[threadIdx.x];
    if (threadIdx.x == N_ARY) s_catcol = g_catcol;
    __syncthreads();

    int warp = threadIdx.x >> 5;
    int lane = threadIdx.x & 31;
    int base = (blockIdx.x * 8 + warp) * 4;            // 4 rows per warp

#pragma unroll
    for (int j = 0; j < 4; j++) {
        const float4* src = reinterpret_cast<const float4*>(
            inputs + (size_t)(base + j) * NUM_ATTR + NUM_CAT);   // 16B-aligned
        float4 v = src[lane];                                     // coalesced 512B
        *reinterpret_cast<float4*>(&s_row[warp][j][lane * 4]) = v;
    }
    __syncwarp();

    int j = lane >> 3;                                 // row within the 4-group
    int g = lane & 7;                                  // slot-quad owner
    int r = base + j;

    int seg = idx_inputs[(size_t)r * NUM_CAT + s_catcol];  // 8-lane broadcast
    seg = min(max(seg, 0), NUM_SEG - 1);               // defensive: never OOB
    if (g == 0) g_catidx[r] = seg;                     // compact copy for gather

    const float* srow = s_row[warp][j];
    float v0 = srow[s_cols[4 * g + 0]];
    float v1 = srow[s_cols[4 * g + 1]];
    float v2 = srow[s_cols[4 * g + 2]];
    float v3 = srow[s_cols[4 * g + 3]];

    float* dst = &g_agg[(size_t)seg * N_ARY + 4 * g];  // 16B-aligned
    asm volatile("red.global.add.v4.f32 [%0], {%1,%2,%3,%4};"
                 :: "l"(dst), "f"(v0), "f"(v1), "f"(v2), "f"(v3)
                 : "memory");
}

// ---------------------------------------------------------------------------
// Kernel 2: gather + scale. Lane j (output rank j) reads its slot's column,
// scales by conf[j], writes coalesced 128B/row. 16 rows/warp for MLP=16
// (gather profiled latency-bound: issue 25%, DRAM 26%).
// ---------------------------------------------------------------------------
__global__ void k_gather(float* __restrict__ out) {
    __shared__ int   s_slot[N_ARY];
    __shared__ float s_conf[N_ARY];
    if (threadIdx.x < N_ARY) {
        s_slot[threadIdx.x] = g_slot_of_rank[threadIdx.x];
        s_conf[threadIdx.x] = g_conf[threadIdx.x];
    }
    __syncthreads();

    int warp = threadIdx.x >> 5;
    int lane = threadIdx.x & 31;
    int  slot = s_slot[lane];
    float conf = s_conf[lane];

    int base = (blockIdx.x * 4 + warp) * 16;           // block=128: 4 warps x 16 rows

    int segs[16];
#pragma unroll
    for (int k = 0; k < 16; k++) segs[k] = g_catidx[base + k];  // batched (MLP)

#pragma unroll
    for (int k = 0; k < 16; k++) {
        out[(size_t)(base + k) * N_ARY + lane] =
            g_agg[(size_t)segs[k] * N_ARY + slot] * conf;
    }
}

// ---------------------------------------------------------------------------
extern "C" void kernel_launch(void* const* d_in, const int* in_sizes, int n_in,
                              void* d_out, int out_size) {
    const float* inputs     = (const float*)d_in[0];
    const int*   idx_inputs = (const int*)d_in[1];     // int32 (JAX x64 off)
    const float* cat_mask   = (const float*)d_in[2];
    const float* num_mask   = (const float*)d_in[3];
    float*       out        = (float*)d_out;

    k_init<<<3126, 256>>>(cat_mask, num_mask);          // block0=setup, rest zero agg
    k_scatter<<<31250, 256>>>(inputs, idx_inputs);      // 8 warps x 4 rows
    k_gather<<<15625, 128>>>(out);                      // 4 warps x 16 rows
}